// round 2
// baseline (speedup 1.0000x reference)
#include <cuda_runtime.h>
#include <math.h>

#define BB   128
#define NTOK 1000
#define NPAD 1024
#define EE   128
#define HH   8
#define DD   16
#define NEGV (-1000000000.0f)
#define SCALE 0.25f

// Scratch (zero-initialized at module load; padding columns n>=1000 stay 0)
__device__ float g_KT [BB * EE * NPAD];   // K  transposed: [b][e][n]
__device__ float g_VT [BB * EE * NPAD];   // V  transposed
__device__ float g_LKT[BB * EE * NPAD];   // logit_k transposed
__device__ float g_fixed[BB * EE];

// ---------------------------------------------------------------------------
// Precompute 1: qkv = node @ Wqkv + bqkv, written transposed into KT/VT/LKT.
// Tiled SGEMM: 64(n) x 64(e3) tile, BK=16, 256 threads, 4x4 per thread.
// ---------------------------------------------------------------------------
__global__ void qkv_gemm(const float* __restrict__ node,
                         const float* __restrict__ W,
                         const float* __restrict__ bias) {
    __shared__ float As[16][64];   // [k][n]
    __shared__ float Bs[16][64];   // [k][e]
    const int b  = blockIdx.z;
    const int n0 = blockIdx.y * 64;
    const int e0 = blockIdx.x * 64;
    const int tx = threadIdx.x, ty = threadIdx.y;
    const int t  = ty * 16 + tx;

    const int an = t >> 2;          // 0..63 (n within tile)
    const int ak = (t & 3) * 4;     // k sub-offset
    const int bk = t >> 4;          // 0..15 (k row)
    const int be = (t & 15) * 4;    // e sub-offset

    float acc[4][4] = {};

    for (int k0 = 0; k0 < 128; k0 += 16) {
        float4 av;
        const int n = n0 + an;
        if (n < NTOK)
            av = *(const float4*)&node[((size_t)b * NTOK + n) * EE + k0 + ak];
        else
            av = make_float4(0.f, 0.f, 0.f, 0.f);
        As[ak + 0][an] = av.x; As[ak + 1][an] = av.y;
        As[ak + 2][an] = av.z; As[ak + 3][an] = av.w;

        float4 bv = *(const float4*)&W[(size_t)(k0 + bk) * 384 + e0 + be];
        *(float4*)&Bs[bk][be] = bv;
        __syncthreads();

        #pragma unroll
        for (int kk = 0; kk < 16; ++kk) {
            float ar[4], br[4];
            #pragma unroll
            for (int i = 0; i < 4; ++i) ar[i] = As[kk][ty * 4 + i];
            #pragma unroll
            for (int j = 0; j < 4; ++j) br[j] = Bs[kk][tx * 4 + j];
            #pragma unroll
            for (int i = 0; i < 4; ++i)
                #pragma unroll
                for (int j = 0; j < 4; ++j)
                    acc[i][j] += ar[i] * br[j];
        }
        __syncthreads();
    }

    #pragma unroll
    for (int i = 0; i < 4; ++i) {
        const int n = n0 + ty * 4 + i;
        if (n >= NTOK) continue;
        #pragma unroll
        for (int j = 0; j < 4; ++j) {
            const int e3 = e0 + tx * 4 + j;
            const float v = acc[i][j] + bias[e3];
            if (e3 < 128)
                g_KT [((size_t)b * EE + e3)       * NPAD + n] = v;
            else if (e3 < 256)
                g_VT [((size_t)b * EE + e3 - 128) * NPAD + n] = v;
            else
                g_LKT[((size_t)b * EE + e3 - 256) * NPAD + n] = v;
        }
    }
}

// ---------------------------------------------------------------------------
// Precompute 2: fixed = graph_embedding @ Wfix + bfix
// ---------------------------------------------------------------------------
__global__ void fixed_kernel(const float* __restrict__ g,
                             const float* __restrict__ Wfix,
                             const float* __restrict__ bfix) {
    const int b = blockIdx.x, e = threadIdx.x;
    __shared__ float gs[EE];
    gs[e] = g[b * EE + e];
    __syncthreads();
    float a = bfix[e];
    #pragma unroll 8
    for (int k = 0; k < EE; ++k) a += gs[k] * Wfix[k * EE + e];
    g_fixed[b * EE + e] = a;
}

// ---------------------------------------------------------------------------
// Persistent decode loop: one block per batch, 999 steps, no grid sync needed.
// ---------------------------------------------------------------------------
__global__ void __launch_bounds__(1024, 1)
decode_loop(const float* __restrict__ node,
            const float* __restrict__ Wstep, const float* __restrict__ bstep,
            const float* __restrict__ Wmlp,  const float* __restrict__ bmlp,
            float* __restrict__ out) {
    const int b    = blockIdx.x;
    const int t    = threadIdx.x;
    const int warp = t >> 5, lane = t & 31;

    __shared__ float sm_p[HH][NPAD];       // softmax numerators (32 KB)
    __shared__ float sm_red[8][EE];        // partial-sum scratch
    __shared__ float sm_wred[32][8];       // per-warp reduction scratch
    __shared__ int   sm_iwred[32];
    __shared__ float sm_cat[2 * EE];       // [first | last]
    __shared__ float sm_q[EE], sm_x[EE], sm_ctx[EE];
    __shared__ float sm_fixed[EE], sm_bstep[EE], sm_bmlp[EE];
    __shared__ unsigned char sm_mask[NPAD];
    __shared__ float sm_maxh[HH], sm_sumh[HH];
    __shared__ int   sm_cur, sm_act;
    __shared__ float sm_total, sm_maxl;

    // ---- init ----
    if (t < EE) {
        sm_cat[t]   = node[((size_t)b * NTOK + 0) * EE + t];   // first (constant)
        sm_fixed[t] = g_fixed[b * EE + t];
        sm_bstep[t] = bstep[t];
        sm_bmlp[t]  = bmlp[t];
    }
    sm_mask[t] = (t == 0 || t >= NTOK) ? 1 : 0;
    if (t == 0) { sm_cur = 0; sm_total = 0.f; }
    __syncthreads();

    #pragma unroll 1
    for (int step = 0; step < NTOK - 1; ++step) {
        // ---- last node embedding into cat[128..255] ----
        if (t < EE) sm_cat[EE + t] = node[((size_t)b * NTOK + sm_cur) * EE + t];
        __syncthreads();

        // ---- q = fixed + cat @ Wstep + bstep  (split j over 8 segs) ----
        {
            const int e = t & 127, seg = t >> 7;
            float a = 0.f;
            const float* w = Wstep + (size_t)(seg * 32) * EE + e;
            #pragma unroll
            for (int j = 0; j < 32; ++j) a += sm_cat[seg * 32 + j] * w[(size_t)j * EE];
            sm_red[seg][e] = a;
        }
        __syncthreads();
        if (t < EE) {
            float a = sm_fixed[t] + sm_bstep[t];
            #pragma unroll
            for (int s = 0; s < 8; ++s) a += sm_red[s][t];
            sm_q[t] = a;
        }
        __syncthreads();

        // ---- attention scores: thread t = token n, 8 heads ----
        float sc[HH];
        {
            const float* kt = g_KT + (size_t)(b * EE) * NPAD + t;
            #pragma unroll
            for (int h = 0; h < HH; ++h) {
                float a = 0.f;
                #pragma unroll
                for (int dd = 0; dd < DD; ++dd)
                    a += sm_q[h * DD + dd] * kt[(size_t)(h * DD + dd) * NPAD];
                sc[h] = sm_mask[t] ? NEGV : a * SCALE;
            }
        }
        // ---- per-head max (warp shuffle + cross-warp) ----
        {
            float m[HH];
            #pragma unroll
            for (int h = 0; h < HH; ++h) {
                m[h] = sc[h];
                #pragma unroll
                for (int o = 16; o > 0; o >>= 1)
                    m[h] = fmaxf(m[h], __shfl_xor_sync(~0u, m[h], o));
            }
            if (lane == 0)
                #pragma unroll
                for (int h = 0; h < HH; ++h) sm_wred[warp][h] = m[h];
        }
        __syncthreads();
        if (warp < HH) {
            float v = sm_wred[lane][warp];
            #pragma unroll
            for (int o = 16; o > 0; o >>= 1)
                v = fmaxf(v, __shfl_xor_sync(~0u, v, o));
            if (lane == 0) sm_maxh[warp] = v;
        }
        __syncthreads();

        // ---- p = exp(s - max); per-head sums ----
        {
            float s[HH];
            #pragma unroll
            for (int h = 0; h < HH; ++h) {
                float p = expf(sc[h] - sm_maxh[h]);
                sm_p[h][t] = p;
                s[h] = p;
                #pragma unroll
                for (int o = 16; o > 0; o >>= 1)
                    s[h] += __shfl_xor_sync(~0u, s[h], o);
            }
            if (lane == 0)
                #pragma unroll
                for (int h = 0; h < HH; ++h) sm_wred[warp][h] = s[h];
        }
        __syncthreads();
        if (warp < HH) {
            float v = sm_wred[lane][warp];
            #pragma unroll
            for (int o = 16; o > 0; o >>= 1)
                v += __shfl_xor_sync(~0u, v, o);
            if (lane == 0) sm_sumh[warp] = v;
        }
        __syncthreads();

        // ---- ctx[e] = (1/sum_h) * sum_n p[h][n] * VT[b][e][n]; warp -> 4 e's ----
        {
            #pragma unroll
            for (int i = 0; i < 4; ++i) {
                const int e = warp * 4 + i;
                const int h = e >> 4;
                const float* vt = g_VT + (size_t)(b * EE + e) * NPAD;
                float a = 0.f;
                #pragma unroll 4
                for (int n = lane; n < NPAD; n += 32) a += sm_p[h][n] * vt[n];
                #pragma unroll
                for (int o = 16; o > 0; o >>= 1)
                    a += __shfl_xor_sync(~0u, a, o);
                if (lane == 0) sm_ctx[e] = a / sm_sumh[h];
            }
        }
        __syncthreads();

        // ---- x = ctx @ Wmlp + bmlp ----
        {
            const int e = t & 127, seg = t >> 7;
            float a = 0.f;
            const float* w = Wmlp + (size_t)(seg * 16) * EE + e;
            #pragma unroll
            for (int j = 0; j < 16; ++j) a += sm_ctx[seg * 16 + j] * w[(size_t)j * EE];
            sm_red[seg][e] = a;
        }
        __syncthreads();
        if (t < EE) {
            float a = sm_bmlp[t];
            #pragma unroll
            for (int s = 0; s < 8; ++s) a += sm_red[s][t];
            sm_x[t] = a;
        }
        __syncthreads();

        // ---- logits[n] = tanh(scale * x . LK[b][:,n]) * 10, masked ----
        float l;
        {
            const float* lk = g_LKT + (size_t)(b * EE) * NPAD + t;
            float a = 0.f;
            #pragma unroll
            for (int e = 0; e < EE; ++e) a += sm_x[e] * lk[(size_t)e * NPAD];
            l = sm_mask[t] ? NEGV : tanhf(a * SCALE) * 10.0f;
        }
        // ---- argmax (first-index tiebreak) ----
        {
            float mv = l; int mi = t;
            #pragma unroll
            for (int o = 16; o > 0; o >>= 1) {
                float ov = __shfl_xor_sync(~0u, mv, o);
                int   oi = __shfl_xor_sync(~0u, mi, o);
                if (ov > mv || (ov == mv && oi < mi)) { mv = ov; mi = oi; }
            }
            if (lane == 0) { sm_wred[warp][0] = mv; sm_iwred[warp] = mi; }
        }
        __syncthreads();
        if (warp == 0) {
            float mv = sm_wred[lane][0]; int mi = sm_iwred[lane];
            #pragma unroll
            for (int o = 16; o > 0; o >>= 1) {
                float ov = __shfl_xor_sync(~0u, mv, o);
                int   oi = __shfl_xor_sync(~0u, mi, o);
                if (ov > mv || (ov == mv && oi < mi)) { mv = ov; mi = oi; }
            }
            if (lane == 0) { sm_maxl = mv; sm_act = mi; }
        }
        __syncthreads();

        // ---- logsumexp; lp = maxl - lse = -log(sum); update state ----
        {
            float p = expf(l - sm_maxl);
            if (t == 1) sm_mask[sm_act] = 1;   // mask not read until next step
            #pragma unroll
            for (int o = 16; o > 0; o >>= 1)
                p += __shfl_xor_sync(~0u, p, o);
            if (lane == 0) sm_wred[warp][0] = p;
        }
        __syncthreads();
        if (warp == 0) {
            float v = sm_wred[lane][0];
            #pragma unroll
            for (int o = 16; o > 0; o >>= 1)
                v += __shfl_xor_sync(~0u, v, o);
            if (lane == 0) { sm_total -= logf(v); sm_cur = sm_act; }
        }
        __syncthreads();
    }

    if (t == 0) out[b] = sm_total;
}

// ---------------------------------------------------------------------------
extern "C" void kernel_launch(void* const* d_in, const int* in_sizes, int n_in,
                              void* d_out, int out_size) {
    const float* node  = (const float*)d_in[0];
    const float* graph = (const float*)d_in[1];
    const float* Wqkv  = (const float*)d_in[2];
    const float* bqkv  = (const float*)d_in[3];
    const float* Wfix  = (const float*)d_in[4];
    const float* bfix  = (const float*)d_in[5];
    const float* Wstep = (const float*)d_in[6];
    const float* bstep = (const float*)d_in[7];
    const float* Wmlp  = (const float*)d_in[8];
    const float* bmlp  = (const float*)d_in[9];
    float* out = (float*)d_out;

    dim3 ggrid(6, 16, BB);      // 384/64 e3-tiles, 1024/64 n-tiles, B
    dim3 gblk(16, 16);
    qkv_gemm<<<ggrid, gblk>>>(node, Wqkv, bqkv);
    fixed_kernel<<<BB, EE>>>(graph, Wfix, bfix);
    decode_loop<<<BB, 1024>>>(node, Wstep, bstep, Wmlp, bmlp, out);
}

// round 3
// speedup vs baseline: 1.8767x; 1.8767x over previous
#include <cuda_runtime.h>
#include <cuda_bf16.h>
#include <math.h>

#define BB   128
#define NTOK 1000
#define NPAD 1024
#define EE   128
#define HH   8
#define DD   16
#define NEGV (-1000000000.0f)
#define SCALE 0.25f

// bf16 scratch. KT/LKT are e-pair-interleaved: element (b, e, n) lives at
//   ((b*64 + e/2)*NPAD + n)*2 + (e&1)
// so a 4B load at bf162 index (b*64+e2)*NPAD + n yields (e=2*e2, e=2*e2+1).
// VT is plain [b][e][n].
__device__ __nv_bfloat16 g_KT [BB * EE * NPAD];
__device__ __nv_bfloat16 g_VT [BB * EE * NPAD];
__device__ __nv_bfloat16 g_LKT[BB * EE * NPAD];
__device__ float g_fixed[BB * EE];

// ---------------------------------------------------------------------------
// Precompute 1: qkv = node @ Wqkv + bqkv  ->  bf16 KT/VT/LKT layouts above.
// ---------------------------------------------------------------------------
__global__ void qkv_gemm(const float* __restrict__ node,
                         const float* __restrict__ W,
                         const float* __restrict__ bias) {
    __shared__ float As[16][64];   // [k][n]
    __shared__ float Bs[16][64];   // [k][e]
    const int b  = blockIdx.z;
    const int n0 = blockIdx.y * 64;
    const int e0 = blockIdx.x * 64;
    const int tx = threadIdx.x, ty = threadIdx.y;
    const int t  = ty * 16 + tx;

    const int an = t >> 2;
    const int ak = (t & 3) * 4;
    const int bk = t >> 4;
    const int be = (t & 15) * 4;

    float acc[4][4] = {};

    for (int k0 = 0; k0 < 128; k0 += 16) {
        float4 av;
        const int n = n0 + an;
        if (n < NTOK)
            av = *(const float4*)&node[((size_t)b * NTOK + n) * EE + k0 + ak];
        else
            av = make_float4(0.f, 0.f, 0.f, 0.f);
        As[ak + 0][an] = av.x; As[ak + 1][an] = av.y;
        As[ak + 2][an] = av.z; As[ak + 3][an] = av.w;

        float4 bv = *(const float4*)&W[(size_t)(k0 + bk) * 384 + e0 + be];
        *(float4*)&Bs[bk][be] = bv;
        __syncthreads();

        #pragma unroll
        for (int kk = 0; kk < 16; ++kk) {
            float ar[4], br[4];
            #pragma unroll
            for (int i = 0; i < 4; ++i) ar[i] = As[kk][ty * 4 + i];
            #pragma unroll
            for (int j = 0; j < 4; ++j) br[j] = Bs[kk][tx * 4 + j];
            #pragma unroll
            for (int i = 0; i < 4; ++i)
                #pragma unroll
                for (int j = 0; j < 4; ++j)
                    acc[i][j] += ar[i] * br[j];
        }
        __syncthreads();
    }

    #pragma unroll
    for (int i = 0; i < 4; ++i) {
        const int n = n0 + ty * 4 + i;
        if (n >= NTOK) continue;
        #pragma unroll
        for (int j = 0; j < 4; ++j) {
            const int e3 = e0 + tx * 4 + j;
            const float v = acc[i][j] + bias[e3];
            const __nv_bfloat16 bv = __float2bfloat16(v);
            if (e3 < 128) {
                const int e = e3;
                g_KT[((size_t)(b * 64 + (e >> 1)) * NPAD + n) * 2 + (e & 1)] = bv;
            } else if (e3 < 256) {
                const int e = e3 - 128;
                g_VT[(size_t)(b * EE + e) * NPAD + n] = bv;
            } else {
                const int e = e3 - 256;
                g_LKT[((size_t)(b * 64 + (e >> 1)) * NPAD + n) * 2 + (e & 1)] = bv;
            }
        }
    }
}

// ---------------------------------------------------------------------------
// Precompute 2: fixed = graph_embedding @ Wfix + bfix
// ---------------------------------------------------------------------------
__global__ void fixed_kernel(const float* __restrict__ g,
                             const float* __restrict__ Wfix,
                             const float* __restrict__ bfix) {
    const int b = blockIdx.x, e = threadIdx.x;
    __shared__ float gs[EE];
    gs[e] = g[b * EE + e];
    __syncthreads();
    float a = bfix[e];
    #pragma unroll 8
    for (int k = 0; k < EE; ++k) a += gs[k] * Wfix[k * EE + e];
    g_fixed[b * EE + e] = a;
}

// ---------------------------------------------------------------------------
// Persistent decode loop: one block per batch, 999 steps.
// ---------------------------------------------------------------------------
__global__ void __launch_bounds__(1024, 1)
decode_loop(const float* __restrict__ node,
            const float* __restrict__ Wstep, const float* __restrict__ bstep,
            const float* __restrict__ Wmlp,  const float* __restrict__ bmlp,
            float* __restrict__ out) {
    const int b    = blockIdx.x;
    const int t    = threadIdx.x;
    const int warp = t >> 5, lane = t & 31;

    __shared__ float sm_p[HH][NPAD];       // softmax numerators (32 KB)
    __shared__ float sm_red[8][EE];
    __shared__ float sm_wred[32][8];
    __shared__ int   sm_iwred[32];
    __shared__ float sm_cat[2 * EE];
    __shared__ float sm_q[EE], sm_x[EE], sm_ctx[EE];
    __shared__ float sm_fixed[EE], sm_bstep[EE], sm_bmlp[EE];
    __shared__ unsigned char sm_mask[NPAD];
    __shared__ float sm_maxh[HH], sm_sumh[HH];
    __shared__ int   sm_cur, sm_act;
    __shared__ float sm_total, sm_maxl;

    if (t < EE) {
        sm_cat[t]   = node[((size_t)b * NTOK + 0) * EE + t];
        sm_fixed[t] = g_fixed[b * EE + t];
        sm_bstep[t] = bstep[t];
        sm_bmlp[t]  = bmlp[t];
    }
    sm_mask[t] = (t == 0 || t >= NTOK) ? 1 : 0;
    if (t == 0) { sm_cur = 0; sm_total = 0.f; }
    __syncthreads();

    const __nv_bfloat162* ktp = (const __nv_bfloat162*)g_KT  + (size_t)b * 64 * NPAD + t;
    const __nv_bfloat162* lkp = (const __nv_bfloat162*)g_LKT + (size_t)b * 64 * NPAD + t;

    #pragma unroll 1
    for (int step = 0; step < NTOK - 1; ++step) {
        if (t < EE) sm_cat[EE + t] = node[((size_t)b * NTOK + sm_cur) * EE + t];
        __syncthreads();

        // ---- q = fixed + cat @ Wstep + bstep ----
        {
            const int e = t & 127, seg = t >> 7;
            float a = 0.f;
            const float* w = Wstep + (size_t)(seg * 32) * EE + e;
            #pragma unroll
            for (int j = 0; j < 32; ++j) a += sm_cat[seg * 32 + j] * w[(size_t)j * EE];
            sm_red[seg][e] = a;
        }
        __syncthreads();
        if (t < EE) {
            float a = sm_fixed[t] + sm_bstep[t];
            #pragma unroll
            for (int s = 0; s < 8; ++s) a += sm_red[s][t];
            sm_q[t] = a;
        }
        __syncthreads();

        // ---- attention scores: thread t = token n, 8 heads, bf16x2 K ----
        float sc[HH];
        {
            #pragma unroll
            for (int h = 0; h < HH; ++h) {
                float a = 0.f;
                #pragma unroll
                for (int d2 = 0; d2 < 8; ++d2) {
                    float2 kv = __bfloat1622float2(ktp[(size_t)(h * 8 + d2) * NPAD]);
                    a += sm_q[h * DD + 2 * d2] * kv.x + sm_q[h * DD + 2 * d2 + 1] * kv.y;
                }
                sc[h] = sm_mask[t] ? NEGV : a * SCALE;
            }
        }
        // ---- per-head max ----
        {
            float m[HH];
            #pragma unroll
            for (int h = 0; h < HH; ++h) {
                m[h] = sc[h];
                #pragma unroll
                for (int o = 16; o > 0; o >>= 1)
                    m[h] = fmaxf(m[h], __shfl_xor_sync(~0u, m[h], o));
            }
            if (lane == 0)
                #pragma unroll
                for (int h = 0; h < HH; ++h) sm_wred[warp][h] = m[h];
        }
        __syncthreads();
        if (warp < HH) {
            float v = sm_wred[lane][warp];
            #pragma unroll
            for (int o = 16; o > 0; o >>= 1)
                v = fmaxf(v, __shfl_xor_sync(~0u, v, o));
            if (lane == 0) sm_maxh[warp] = v;
        }
        __syncthreads();

        // ---- p = exp(s - max); per-head sums ----
        {
            float s[HH];
            #pragma unroll
            for (int h = 0; h < HH; ++h) {
                float p = expf(sc[h] - sm_maxh[h]);
                sm_p[h][t] = p;
                s[h] = p;
                #pragma unroll
                for (int o = 16; o > 0; o >>= 1)
                    s[h] += __shfl_xor_sync(~0u, s[h], o);
            }
            if (lane == 0)
                #pragma unroll
                for (int h = 0; h < HH; ++h) sm_wred[warp][h] = s[h];
        }
        __syncthreads();
        if (warp < HH) {
            float v = sm_wred[lane][warp];
            #pragma unroll
            for (int o = 16; o > 0; o >>= 1)
                v += __shfl_xor_sync(~0u, v, o);
            if (lane == 0) sm_sumh[warp] = v;
        }
        __syncthreads();

        // ---- ctx[e]: warp -> 4 e's, bf16x2 V along n ----
        {
            #pragma unroll
            for (int i = 0; i < 4; ++i) {
                const int e = warp * 4 + i;
                const int h = e >> 4;
                const __nv_bfloat162* vt =
                    (const __nv_bfloat162*)g_VT + (size_t)(b * EE + e) * (NPAD / 2);
                float a = 0.f;
                #pragma unroll 4
                for (int n2 = lane; n2 < NPAD / 2; n2 += 32) {
                    float2 v = __bfloat1622float2(vt[n2]);
                    a += sm_p[h][2 * n2] * v.x + sm_p[h][2 * n2 + 1] * v.y;
                }
                #pragma unroll
                for (int o = 16; o > 0; o >>= 1)
                    a += __shfl_xor_sync(~0u, a, o);
                if (lane == 0) sm_ctx[e] = a / sm_sumh[h];
            }
        }
        __syncthreads();

        // ---- x = ctx @ Wmlp + bmlp ----
        {
            const int e = t & 127, seg = t >> 7;
            float a = 0.f;
            const float* w = Wmlp + (size_t)(seg * 16) * EE + e;
            #pragma unroll
            for (int j = 0; j < 16; ++j) a += sm_ctx[seg * 16 + j] * w[(size_t)j * EE];
            sm_red[seg][e] = a;
        }
        __syncthreads();
        if (t < EE) {
            float a = sm_bmlp[t];
            #pragma unroll
            for (int s = 0; s < 8; ++s) a += sm_red[s][t];
            sm_x[t] = a;
        }
        __syncthreads();

        // ---- logits[n] = tanh(scale * x . LK[:,n]) * 10, masked; bf16x2 LK ----
        float l;
        {
            float a = 0.f;
            #pragma unroll
            for (int e2 = 0; e2 < 64; ++e2) {
                float2 lk = __bfloat1622float2(lkp[(size_t)e2 * NPAD]);
                a += sm_x[2 * e2] * lk.x + sm_x[2 * e2 + 1] * lk.y;
            }
            l = sm_mask[t] ? NEGV : tanhf(a * SCALE) * 10.0f;
        }
        // ---- argmax (first-index tiebreak) ----
        {
            float mv = l; int mi = t;
            #pragma unroll
            for (int o = 16; o > 0; o >>= 1) {
                float ov = __shfl_xor_sync(~0u, mv, o);
                int   oi = __shfl_xor_sync(~0u, mi, o);
                if (ov > mv || (ov == mv && oi < mi)) { mv = ov; mi = oi; }
            }
            if (lane == 0) { sm_wred[warp][0] = mv; sm_iwred[warp] = mi; }
        }
        __syncthreads();
        if (warp == 0) {
            float mv = sm_wred[lane][0]; int mi = sm_iwred[lane];
            #pragma unroll
            for (int o = 16; o > 0; o >>= 1) {
                float ov = __shfl_xor_sync(~0u, mv, o);
                int   oi = __shfl_xor_sync(~0u, mi, o);
                if (ov > mv || (ov == mv && oi < mi)) { mv = ov; mi = oi; }
            }
            if (lane == 0) { sm_maxl = mv; sm_act = mi; }
        }
        __syncthreads();

        // ---- logsumexp; update state ----
        {
            float p = expf(l - sm_maxl);
            if (t == 1) sm_mask[sm_act] = 1;
            #pragma unroll
            for (int o = 16; o > 0; o >>= 1)
                p += __shfl_xor_sync(~0u, p, o);
            if (lane == 0) sm_wred[warp][0] = p;
        }
        __syncthreads();
        if (warp == 0) {
            float v = sm_wred[lane][0];
            #pragma unroll
            for (int o = 16; o > 0; o >>= 1)
                v += __shfl_xor_sync(~0u, v, o);
            if (lane == 0) { sm_total -= logf(v); sm_cur = sm_act; }
        }
        __syncthreads();
    }

    if (t == 0) out[b] = sm_total;
}

// ---------------------------------------------------------------------------
extern "C" void kernel_launch(void* const* d_in, const int* in_sizes, int n_in,
                              void* d_out, int out_size) {
    const float* node  = (const float*)d_in[0];
    const float* graph = (const float*)d_in[1];
    const float* Wqkv  = (const float*)d_in[2];
    const float* bqkv  = (const float*)d_in[3];
    const float* Wfix  = (const float*)d_in[4];
    const float* bfix  = (const float*)d_in[5];
    const float* Wstep = (const float*)d_in[6];
    const float* bstep = (const float*)d_in[7];
    const float* Wmlp  = (const float*)d_in[8];
    const float* bmlp  = (const float*)d_in[9];
    float* out = (float*)d_out;

    dim3 ggrid(6, 16, BB);
    dim3 gblk(16, 16);
    qkv_gemm<<<ggrid, gblk>>>(node, Wqkv, bqkv);
    fixed_kernel<<<BB, EE>>>(graph, Wfix, bfix);
    decode_loop<<<BB, 1024>>>(node, Wstep, bstep, Wmlp, bmlp, out);
}

// round 4
// speedup vs baseline: 2.5169x; 1.3411x over previous
#include <cuda_runtime.h>
#include <cuda_bf16.h>
#include <math.h>

#define BB   128
#define NTOK 1000
#define NPAD 1024
#define EE   128
#define HH   8
#define NEGV (-1000000000.0f)
#define SCALE 0.25f
#define WSTRIDE 65   // bf162 row stride for weight caches (odd => conflict-free)

// K and LK quad-interleaved over e: (b,e,n) -> bf16 index ((b*32+(e>>2))*NPAD+n)*4+(e&3)
// V plain [b][e][n] bf16. uint2 declarations guarantee 8B alignment.
__device__ uint2 g_K4 [BB * 32 * NPAD];
__device__ uint2 g_LK4[BB * 32 * NPAD];
__device__ uint2 g_V4 [BB * EE * NPAD / 4];
__device__ float g_fixed[BB * EE];

// ---------------------------------------------------------------------------
// Precompute 1: qkv = node @ Wqkv + bqkv  ->  bf16 K/V/LK layouts above.
// ---------------------------------------------------------------------------
__global__ void qkv_gemm(const float* __restrict__ node,
                         const float* __restrict__ W,
                         const float* __restrict__ bias) {
    __shared__ float As[16][64];
    __shared__ float Bs[16][64];
    const int b  = blockIdx.z;
    const int n0 = blockIdx.y * 64;
    const int e0 = blockIdx.x * 64;
    const int tx = threadIdx.x, ty = threadIdx.y;
    const int t  = ty * 16 + tx;

    const int an = t >> 2;
    const int ak = (t & 3) * 4;
    const int bk = t >> 4;
    const int be = (t & 15) * 4;

    float acc[4][4] = {};

    for (int k0 = 0; k0 < 128; k0 += 16) {
        float4 av;
        const int n = n0 + an;
        if (n < NTOK)
            av = *(const float4*)&node[((size_t)b * NTOK + n) * EE + k0 + ak];
        else
            av = make_float4(0.f, 0.f, 0.f, 0.f);
        As[ak + 0][an] = av.x; As[ak + 1][an] = av.y;
        As[ak + 2][an] = av.z; As[ak + 3][an] = av.w;

        float4 bv = *(const float4*)&W[(size_t)(k0 + bk) * 384 + e0 + be];
        *(float4*)&Bs[bk][be] = bv;
        __syncthreads();

        #pragma unroll
        for (int kk = 0; kk < 16; ++kk) {
            float ar[4], br[4];
            #pragma unroll
            for (int i = 0; i < 4; ++i) ar[i] = As[kk][ty * 4 + i];
            #pragma unroll
            for (int j = 0; j < 4; ++j) br[j] = Bs[kk][tx * 4 + j];
            #pragma unroll
            for (int i = 0; i < 4; ++i)
                #pragma unroll
                for (int j = 0; j < 4; ++j)
                    acc[i][j] += ar[i] * br[j];
        }
        __syncthreads();
    }

    __nv_bfloat16* K  = (__nv_bfloat16*)g_K4;
    __nv_bfloat16* LK = (__nv_bfloat16*)g_LK4;
    __nv_bfloat16* V  = (__nv_bfloat16*)g_V4;

    #pragma unroll
    for (int i = 0; i < 4; ++i) {
        const int n = n0 + ty * 4 + i;
        if (n >= NTOK) continue;
        #pragma unroll
        for (int j = 0; j < 4; ++j) {
            const int e3 = e0 + tx * 4 + j;
            const float v = acc[i][j] + bias[e3];
            const __nv_bfloat16 bv = __float2bfloat16(v);
            if (e3 < 128) {
                const int e = e3;
                K[((size_t)(b * 32 + (e >> 2)) * NPAD + n) * 4 + (e & 3)] = bv;
            } else if (e3 < 256) {
                const int e = e3 - 128;
                V[(size_t)(b * EE + e) * NPAD + n] = bv;
            } else {
                const int e = e3 - 256;
                LK[((size_t)(b * 32 + (e >> 2)) * NPAD + n) * 4 + (e & 3)] = bv;
            }
        }
    }
}

// ---------------------------------------------------------------------------
// Precompute 2: fixed = graph_embedding @ Wfix + bfix
// ---------------------------------------------------------------------------
__global__ void fixed_kernel(const float* __restrict__ g,
                             const float* __restrict__ Wfix,
                             const float* __restrict__ bfix) {
    const int b = blockIdx.x, e = threadIdx.x;
    __shared__ float gs[EE];
    gs[e] = g[b * EE + e];
    __syncthreads();
    float a = bfix[e];
    #pragma unroll 8
    for (int k = 0; k < EE; ++k) a += gs[k] * Wfix[k * EE + e];
    g_fixed[b * EE + e] = a;
}

__device__ __forceinline__ float tanh_fast(float x) {
    float r;
    asm("tanh.approx.f32 %0, %1;" : "=f"(r) : "f"(x));
    return r;
}

// ---------------------------------------------------------------------------
// Persistent decode loop: one block per batch, 999 steps, 7 syncs/step.
// ---------------------------------------------------------------------------
__global__ void __launch_bounds__(1024, 1)
decode_loop(const float* __restrict__ node,
            const float* __restrict__ Wstep, const float* __restrict__ bstep,
            const float* __restrict__ Wmlp,  const float* __restrict__ bmlp,
            float* __restrict__ out) {
    const int b    = blockIdx.x;
    const int t    = threadIdx.x;
    const int warp = t >> 5, lane = t & 31;

    extern __shared__ char dyn[];
    float*           smp = (float*)dyn;                                 // 8*1024 f32 = 32768
    __nv_bfloat162*  wq  = (__nv_bfloat162*)(dyn + 32768);              // 128*65*4  = 33280
    __nv_bfloat162*  wm  = (__nv_bfloat162*)(dyn + 32768 + 33280);      // 33280

    __shared__ float sm_wred[32 * 9];
    __shared__ int   sm_iwred[32];
    __shared__ float sm_last[EE], sm_q[EE], sm_x[EE], sm_ctx[EE];
    __shared__ float sm_qbase[EE], sm_bmlp[EE];
    __shared__ unsigned char sm_mask[NPAD];
    __shared__ int   sm_cur, sm_act;
    __shared__ float sm_total;

    // ---- init: weight caches (bf162, [e][j2] layout, stride 65) ----
    for (int idx = t; idx < 128 * 64; idx += 1024) {
        const int j2 = idx >> 7, e = idx & 127;
        wq[e * WSTRIDE + j2] = __floats2bfloat162_rn(
            Wstep[(size_t)(128 + 2 * j2) * EE + e],
            Wstep[(size_t)(129 + 2 * j2) * EE + e]);
        wm[e * WSTRIDE + j2] = __floats2bfloat162_rn(
            Wmlp[(size_t)(2 * j2) * EE + e],
            Wmlp[(size_t)(2 * j2 + 1) * EE + e]);
    }
    if (t < EE) {
        sm_last[t] = node[((size_t)b * NTOK + 0) * EE + t];   // first, for q_base
        sm_bmlp[t] = bmlp[t];
    }
    sm_mask[t] = (t == 0 || t >= NTOK) ? 1 : 0;
    if (t == 0) { sm_cur = 0; sm_total = 0.f; }
    __syncthreads();

    // ---- q_base[e] = fixed + bstep + first @ Wstep[:128] (once) ----
    {
        const int e = t >> 3, seg = t & 7;
        float a = 0.f;
        #pragma unroll
        for (int i = 0; i < 16; ++i) {
            const int j = seg * 16 + i;
            a += sm_last[j] * Wstep[(size_t)j * EE + e];
        }
        a += __shfl_xor_sync(~0u, a, 1);
        a += __shfl_xor_sync(~0u, a, 2);
        a += __shfl_xor_sync(~0u, a, 4);
        if ((t & 7) == 0) sm_qbase[e] = a + g_fixed[b * EE + e] + bstep[e];
    }
    __syncthreads();

    const uint2* kq = g_K4  + (size_t)b * 32 * NPAD + t;
    const uint2* lq = g_LK4 + (size_t)b * 32 * NPAD + t;

    #pragma unroll 1
    for (int step = 0; step < NTOK - 1; ++step) {
        // ---- A: fetch last-node embedding ----
        if (t < EE) sm_last[t] = node[((size_t)b * NTOK + sm_cur) * EE + t];
        __syncthreads();   // S1

        // ---- B: q[e] = qbase[e] + last @ Wstep[128:]  (thread = (e, seg)) ----
        {
            const int e = t >> 3, seg = t & 7;
            float a = 0.f;
            #pragma unroll
            for (int i = 0; i < 8; ++i) {
                const int j2 = seg * 8 + i;
                const __nv_bfloat162 w = wq[e * WSTRIDE + j2];
                a += sm_last[2 * j2]     * __bfloat162float(w.x)
                   + sm_last[2 * j2 + 1] * __bfloat162float(w.y);
            }
            a += __shfl_xor_sync(~0u, a, 1);
            a += __shfl_xor_sync(~0u, a, 2);
            a += __shfl_xor_sync(~0u, a, 4);
            if ((t & 7) == 0) sm_q[e] = a + sm_qbase[e];
        }
        __syncthreads();   // S2

        // ---- C: scores (no max-shift), p = exp, store smp, per-warp head sums ----
        {
            const bool msk = sm_mask[t];
            #pragma unroll
            for (int h = 0; h < HH; ++h) {
                float a = 0.f;
                #pragma unroll
                for (int c = 0; c < 4; ++c) {
                    const uint2 r = kq[(size_t)(4 * h + c) * NPAD];
                    const float2 k0 = __bfloat1622float2(*(const __nv_bfloat162*)&r.x);
                    const float2 k1 = __bfloat1622float2(*(const __nv_bfloat162*)&r.y);
                    const float4 qv = *(const float4*)&sm_q[h * 16 + 4 * c];
                    a += qv.x * k0.x + qv.y * k0.y + qv.z * k1.x + qv.w * k1.y;
                }
                float p = msk ? 0.f : __expf(a * SCALE);
                smp[h * NPAD + t] = p;
                #pragma unroll
                for (int o = 16; o > 0; o >>= 1)
                    p += __shfl_xor_sync(~0u, p, o);
                if (lane == 0) sm_wred[warp * 9 + h] = p;
            }
        }
        __syncthreads();   // S3

        // ---- D: ctx[e] (warp -> 4 e's); own-head sum reduced from wred ----
        {
            const int h = warp >> 2;
            float sv = sm_wred[lane * 9 + h];
            #pragma unroll
            for (int o = 16; o > 0; o >>= 1)
                sv += __shfl_xor_sync(~0u, sv, o);
            const float inv = 1.0f / sv;
            #pragma unroll
            for (int i = 0; i < 4; ++i) {
                const int e = warp * 4 + i;
                const uint2* vt = g_V4 + (size_t)(b * EE + e) * (NPAD / 4);
                float a = 0.f;
                #pragma unroll
                for (int k = 0; k < 8; ++k) {
                    const int idx = k * 32 + lane;
                    const uint2 r = vt[idx];
                    const float2 v0 = __bfloat1622float2(*(const __nv_bfloat162*)&r.x);
                    const float2 v1 = __bfloat1622float2(*(const __nv_bfloat162*)&r.y);
                    const float4 pp = *(const float4*)&smp[h * NPAD + 4 * idx];
                    a += pp.x * v0.x + pp.y * v0.y + pp.z * v1.x + pp.w * v1.y;
                }
                #pragma unroll
                for (int o = 16; o > 0; o >>= 1)
                    a += __shfl_xor_sync(~0u, a, o);
                if (lane == 0) sm_ctx[e] = a * inv;
            }
        }
        __syncthreads();   // S4

        // ---- E: x[e] = ctx @ Wmlp + bmlp ----
        {
            const int e = t >> 3, seg = t & 7;
            float a = 0.f;
            #pragma unroll
            for (int i = 0; i < 8; ++i) {
                const int j2 = seg * 8 + i;
                const __nv_bfloat162 w = wm[e * WSTRIDE + j2];
                a += sm_ctx[2 * j2]     * __bfloat162float(w.x)
                   + sm_ctx[2 * j2 + 1] * __bfloat162float(w.y);
            }
            a += __shfl_xor_sync(~0u, a, 1);
            a += __shfl_xor_sync(~0u, a, 2);
            a += __shfl_xor_sync(~0u, a, 4);
            if ((t & 7) == 0) sm_x[e] = a + sm_bmlp[e];
        }
        __syncthreads();   // S5

        // ---- F: logits; fused argmax(a) + sum exp(l); tanh.approx for sum ----
        {
            const bool msk = sm_mask[t];
            float a = 0.f;
            #pragma unroll
            for (int e4 = 0; e4 < 32; ++e4) {
                const uint2 r = lq[(size_t)e4 * NPAD];
                const float2 l0 = __bfloat1622float2(*(const __nv_bfloat162*)&r.x);
                const float2 l1 = __bfloat1622float2(*(const __nv_bfloat162*)&r.y);
                const float4 xv = *(const float4*)&sm_x[4 * e4];
                a += xv.x * l0.x + xv.y * l0.y + xv.z * l1.x + xv.w * l1.y;
            }
            // argmax over raw a (tanh monotonic); masked excluded via NEGV
            float mv = msk ? NEGV : a;
            int   mi = t;
            float s  = msk ? 0.f : __expf(tanh_fast(a * SCALE) * 10.0f);
            #pragma unroll
            for (int o = 16; o > 0; o >>= 1) {
                const float ov = __shfl_xor_sync(~0u, mv, o);
                const int   oi = __shfl_xor_sync(~0u, mi, o);
                s += __shfl_xor_sync(~0u, s, o);
                if (ov > mv || (ov == mv && oi < mi)) { mv = ov; mi = oi; }
            }
            if (lane == 0) {
                sm_wred[warp * 9 + 0] = mv;
                sm_wred[warp * 9 + 1] = s;
                sm_iwred[warp] = mi;
            }
        }
        __syncthreads();   // S6

        // ---- G: final reduce (warp 0); update total/cur/mask ----
        if (warp == 0) {
            float mv = sm_wred[lane * 9 + 0];
            float s  = sm_wred[lane * 9 + 1];
            int   mi = sm_iwred[lane];
            #pragma unroll
            for (int o = 16; o > 0; o >>= 1) {
                const float ov = __shfl_xor_sync(~0u, mv, o);
                const int   oi = __shfl_xor_sync(~0u, mi, o);
                s += __shfl_xor_sync(~0u, s, o);
                if (ov > mv || (ov == mv && oi < mi)) { mv = ov; mi = oi; }
            }
            if (lane == 0) {
                const float l_act = tanhf(mv * SCALE) * 10.0f;  // precise for winner
                sm_total += l_act - logf(s);
                sm_cur = mi;
                sm_act = mi;
                sm_mask[mi] = 1;
            }
        }
        __syncthreads();   // S7
    }

    if (t == 0) out[b] = sm_total;
}

// ---------------------------------------------------------------------------
extern "C" void kernel_launch(void* const* d_in, const int* in_sizes, int n_in,
                              void* d_out, int out_size) {
    const float* node  = (const float*)d_in[0];
    const float* graph = (const float*)d_in[1];
    const float* Wqkv  = (const float*)d_in[2];
    const float* bqkv  = (const float*)d_in[3];
    const float* Wfix  = (const float*)d_in[4];
    const float* bfix  = (const float*)d_in[5];
    const float* Wstep = (const float*)d_in[6];
    const float* bstep = (const float*)d_in[7];
    const float* Wmlp  = (const float*)d_in[8];
    const float* bmlp  = (const float*)d_in[9];
    float* out = (float*)d_out;

    const int dyn_bytes = 32768 + 33280 + 33280;   // smp + wq + wm = 99328
    cudaFuncSetAttribute(decode_loop, cudaFuncAttributeMaxDynamicSharedMemorySize,
                         dyn_bytes);

    dim3 ggrid(6, 16, BB);
    dim3 gblk(16, 16);
    qkv_gemm<<<ggrid, gblk>>>(node, Wqkv, bqkv);
    fixed_kernel<<<BB, EE>>>(graph, Wfix, bfix);
    decode_loop<<<BB, 1024, dyn_bytes>>>(node, Wstep, bstep, Wmlp, bmlp, out);
}

// round 5
// speedup vs baseline: 2.8801x; 1.1443x over previous
#include <cuda_runtime.h>
#include <cuda_bf16.h>
#include <math.h>

#define BB   128
#define NTOK 1000
#define NPAD 1024
#define EE   128
#define HH   8
#define NEGV (-1000000000.0f)
#define SCALE 0.25f

// K and G quad-interleaved over e/c: (b,e,n) -> bf16 ((b*32+(e>>2))*NPAD+n)*4+(e&3)
// V plain [b][e][n] bf16 (uint2 = 4 consecutive n). LKp plain [b][e][n] bf16.
__device__ uint2 g_K4 [BB * 32 * NPAD];
__device__ uint2 g_G4 [BB * 32 * NPAD];
__device__ uint2 g_V4 [BB * EE * NPAD / 4];
__device__ __nv_bfloat16 g_LKp[BB * EE * NPAD];
__device__ float g_SK   [(size_t)BB * NTOK * EE];   // node @ Wstep[128:]
__device__ float g_qbase[BB * EE];
__device__ float g_blk  [BB * NPAD];                // bmlp . LK[:,n]

// ---------------------------------------------------------------------------
// Precompute 1: qkv = node @ Wqkv + bqkv -> K4 / V4 / LKp
// ---------------------------------------------------------------------------
__global__ void qkv_gemm(const float* __restrict__ node,
                         const float* __restrict__ W,
                         const float* __restrict__ bias) {
    __shared__ float As[16][64];
    __shared__ float Bs[16][64];
    const int b  = blockIdx.z;
    const int n0 = blockIdx.y * 64;
    const int e0 = blockIdx.x * 64;
    const int tx = threadIdx.x, ty = threadIdx.y;
    const int t  = ty * 16 + tx;
    const int an = t >> 2, ak = (t & 3) * 4;
    const int bk = t >> 4, be = (t & 15) * 4;

    float acc[4][4] = {};
    for (int k0 = 0; k0 < 128; k0 += 16) {
        float4 av;
        const int n = n0 + an;
        if (n < NTOK) av = *(const float4*)&node[((size_t)b * NTOK + n) * EE + k0 + ak];
        else          av = make_float4(0.f, 0.f, 0.f, 0.f);
        As[ak + 0][an] = av.x; As[ak + 1][an] = av.y;
        As[ak + 2][an] = av.z; As[ak + 3][an] = av.w;
        *(float4*)&Bs[bk][be] = *(const float4*)&W[(size_t)(k0 + bk) * 384 + e0 + be];
        __syncthreads();
        #pragma unroll
        for (int kk = 0; kk < 16; ++kk) {
            float ar[4], br[4];
            #pragma unroll
            for (int i = 0; i < 4; ++i) ar[i] = As[kk][ty * 4 + i];
            #pragma unroll
            for (int j = 0; j < 4; ++j) br[j] = Bs[kk][tx * 4 + j];
            #pragma unroll
            for (int i = 0; i < 4; ++i)
                #pragma unroll
                for (int j = 0; j < 4; ++j) acc[i][j] += ar[i] * br[j];
        }
        __syncthreads();
    }

    __nv_bfloat16* K = (__nv_bfloat16*)g_K4;
    __nv_bfloat16* V = (__nv_bfloat16*)g_V4;
    #pragma unroll
    for (int i = 0; i < 4; ++i) {
        const int n = n0 + ty * 4 + i;
        if (n >= NTOK) continue;
        #pragma unroll
        for (int j = 0; j < 4; ++j) {
            const int e3 = e0 + tx * 4 + j;
            const __nv_bfloat16 bv = __float2bfloat16(acc[i][j] + bias[e3]);
            if (e3 < 128) {
                const int e = e3;
                K[((size_t)(b * 32 + (e >> 2)) * NPAD + n) * 4 + (e & 3)] = bv;
            } else if (e3 < 256) {
                const int e = e3 - 128;
                V[(size_t)(b * EE + e) * NPAD + n] = bv;
            } else {
                const int e = e3 - 256;
                g_LKp[(size_t)(b * EE + e) * NPAD + n] = bv;
            }
        }
    }
}

// ---------------------------------------------------------------------------
// Precompute 2: SK[b][n][e] = node[b,n] @ Wstep[128:256]  (fp32)
// ---------------------------------------------------------------------------
__global__ void sk_gemm(const float* __restrict__ node,
                        const float* __restrict__ Wstep) {
    __shared__ float As[16][64];
    __shared__ float Bs[16][64];
    const float* W2 = Wstep + 128 * EE;
    const int b  = blockIdx.z;
    const int n0 = blockIdx.y * 64;
    const int e0 = blockIdx.x * 64;
    const int tx = threadIdx.x, ty = threadIdx.y;
    const int t  = ty * 16 + tx;
    const int an = t >> 2, ak = (t & 3) * 4;
    const int bk = t >> 4, be = (t & 15) * 4;

    float acc[4][4] = {};
    for (int k0 = 0; k0 < 128; k0 += 16) {
        float4 av;
        const int n = n0 + an;
        if (n < NTOK) av = *(const float4*)&node[((size_t)b * NTOK + n) * EE + k0 + ak];
        else          av = make_float4(0.f, 0.f, 0.f, 0.f);
        As[ak + 0][an] = av.x; As[ak + 1][an] = av.y;
        As[ak + 2][an] = av.z; As[ak + 3][an] = av.w;
        *(float4*)&Bs[bk][be] = *(const float4*)&W2[(size_t)(k0 + bk) * EE + e0 + be];
        __syncthreads();
        #pragma unroll
        for (int kk = 0; kk < 16; ++kk) {
            float ar[4], br[4];
            #pragma unroll
            for (int i = 0; i < 4; ++i) ar[i] = As[kk][ty * 4 + i];
            #pragma unroll
            for (int j = 0; j < 4; ++j) br[j] = Bs[kk][tx * 4 + j];
            #pragma unroll
            for (int i = 0; i < 4; ++i)
                #pragma unroll
                for (int j = 0; j < 4; ++j) acc[i][j] += ar[i] * br[j];
        }
        __syncthreads();
    }
    #pragma unroll
    for (int i = 0; i < 4; ++i) {
        const int n = n0 + ty * 4 + i;
        if (n >= NTOK) continue;
        #pragma unroll
        for (int j = 0; j < 4; ++j)
            g_SK[((size_t)b * NTOK + n) * EE + e0 + tx * 4 + j] = acc[i][j];
    }
}

// ---------------------------------------------------------------------------
// Precompute 3: G[b][c][n] = Wmlp[c][:] . LK[b][:][n]  -> quad-interleaved bf16
// ---------------------------------------------------------------------------
__global__ void g_gemm(const float* __restrict__ Wmlp) {
    __shared__ float As[16][64];   // [e][c]
    __shared__ float Bs[16][64];   // [e][n]
    const int b  = blockIdx.z;
    const int n0 = blockIdx.y * 64;
    const int c0 = blockIdx.x * 64;
    const int tx = threadIdx.x, ty = threadIdx.y;
    const int t  = ty * 16 + tx;
    const int ac = t >> 2, ae = (t & 3) * 4;
    const int bk = t >> 4, bn = (t & 15) * 4;

    float acc[4][4] = {};
    for (int k0 = 0; k0 < 128; k0 += 16) {
        // A: Wmlp[c][e] row-major over e
        const float4 av = *(const float4*)&Wmlp[(size_t)(c0 + ac) * EE + k0 + ae];
        As[ae + 0][ac] = av.x; As[ae + 1][ac] = av.y;
        As[ae + 2][ac] = av.z; As[ae + 3][ac] = av.w;
        // B: LKp[b][e][n], bf16, 4 consecutive n
        const uint2 r = *(const uint2*)&g_LKp[(size_t)(b * EE + k0 + bk) * NPAD + n0 + bn];
        const float2 v0 = __bfloat1622float2(*(const __nv_bfloat162*)&r.x);
        const float2 v1 = __bfloat1622float2(*(const __nv_bfloat162*)&r.y);
        Bs[bk][bn + 0] = v0.x; Bs[bk][bn + 1] = v0.y;
        Bs[bk][bn + 2] = v1.x; Bs[bk][bn + 3] = v1.y;
        __syncthreads();
        #pragma unroll
        for (int kk = 0; kk < 16; ++kk) {
            float ar[4], br[4];
            #pragma unroll
            for (int i = 0; i < 4; ++i) ar[i] = As[kk][ty * 4 + i];
            #pragma unroll
            for (int j = 0; j < 4; ++j) br[j] = Bs[kk][tx * 4 + j];
            #pragma unroll
            for (int i = 0; i < 4; ++i)
                #pragma unroll
                for (int j = 0; j < 4; ++j) acc[i][j] += ar[i] * br[j];
        }
        __syncthreads();
    }
    __nv_bfloat16* G = (__nv_bfloat16*)g_G4;
    #pragma unroll
    for (int i = 0; i < 4; ++i) {
        const int c = c0 + ty * 4 + i;
        #pragma unroll
        for (int j = 0; j < 4; ++j) {
            const int n = n0 + tx * 4 + j;
            G[((size_t)(b * 32 + (c >> 2)) * NPAD + n) * 4 + (c & 3)] =
                __float2bfloat16(acc[i][j]);
        }
    }
}

// ---------------------------------------------------------------------------
// Precompute 4: blk[b][n] = bmlp . LK[b][:][n]
// ---------------------------------------------------------------------------
__global__ void blk_kernel(const float* __restrict__ bmlp) {
    const int b = blockIdx.x, n = threadIdx.x;
    __shared__ float bm[EE];
    if (n < EE) bm[n] = bmlp[n];
    __syncthreads();
    float a = 0.f;
    #pragma unroll 8
    for (int e = 0; e < EE; ++e)
        a += bm[e] * __bfloat162float(g_LKp[(size_t)(b * EE + e) * NPAD + n]);
    g_blk[b * NPAD + n] = a;
}

// ---------------------------------------------------------------------------
// Precompute 5: qbase = graph@Wfix + bfix + bstep + first@Wstep[:128]
// ---------------------------------------------------------------------------
__global__ void qbase_kernel(const float* __restrict__ g,
                             const float* __restrict__ node,
                             const float* __restrict__ Wfix,
                             const float* __restrict__ bfix,
                             const float* __restrict__ Wstep,
                             const float* __restrict__ bstep) {
    const int b = blockIdx.x, e = threadIdx.x;
    __shared__ float gs[EE], fs[EE];
    gs[e] = g[b * EE + e];
    fs[e] = node[(size_t)b * NTOK * EE + e];
    __syncthreads();
    float a = bfix[e] + bstep[e];
    #pragma unroll 4
    for (int k = 0; k < EE; ++k) {
        a += gs[k] * Wfix[(size_t)k * EE + e];
        a += fs[k] * Wstep[(size_t)k * EE + e];
    }
    g_qbase[b * EE + e] = a;
}

__device__ __forceinline__ float tanh_fast(float x) {
    float r;
    asm("tanh.approx.f32 %0, %1;" : "=f"(r) : "f"(x));
    return r;
}

// ---------------------------------------------------------------------------
// Persistent decode loop: one block per batch, 999 steps, 4 syncs/step.
// ---------------------------------------------------------------------------
__global__ void __launch_bounds__(1024, 1)
decode_loop(float* __restrict__ out) {
    const int b    = blockIdx.x;
    const int t    = threadIdx.x;
    const int warp = t >> 5, lane = t & 31;

    __shared__ __align__(16) float smp[HH * NPAD];   // 32 KB
    __shared__ float sm_blk[NPAD];                   // 4 KB
    __shared__ float sm_wred[32 * 9];
    __shared__ int   sm_iwred[32];
    __shared__ __align__(16) float sm_q[EE];
    __shared__ __align__(16) float sm_ctx[EE];
    __shared__ float sm_qbase[EE];
    __shared__ unsigned char sm_mask[NPAD];

    if (t < EE) sm_qbase[t] = g_qbase[b * EE + t];
    sm_blk[t]  = g_blk[b * NPAD + t];
    sm_mask[t] = (t == 0 || t >= NTOK) ? 1 : 0;
    __syncthreads();

    const uint2* kq = g_K4 + (size_t)b * 32 * NPAD + t;
    const uint2* gq = g_G4 + (size_t)b * 32 * NPAD + t;
    int   cur   = 0;
    float total = 0.f;

    #pragma unroll 1
    for (int step = 0; step < NTOK - 1; ++step) {
        // ---- q row: qbase + SK[cur] ----
        if (t < EE)
            sm_q[t] = sm_qbase[t] + g_SK[((size_t)b * NTOK + cur) * EE + t];
        __syncthreads();   // S1 (also publishes mask update from prev step)

        // ---- C: scores, p = exp (no max-shift), per-warp head sums ----
        const bool msk = sm_mask[t];
        #pragma unroll
        for (int h = 0; h < HH; ++h) {
            float a = 0.f;
            #pragma unroll
            for (int c = 0; c < 4; ++c) {
                const uint2 r = kq[(size_t)(4 * h + c) * NPAD];
                const float2 k0 = __bfloat1622float2(*(const __nv_bfloat162*)&r.x);
                const float2 k1 = __bfloat1622float2(*(const __nv_bfloat162*)&r.y);
                const float4 qv = *(const float4*)&sm_q[h * 16 + 4 * c];
                a += qv.x * k0.x + qv.y * k0.y + qv.z * k1.x + qv.w * k1.y;
            }
            float p = msk ? 0.f : __expf(a * SCALE);
            smp[h * NPAD + t] = p;
            #pragma unroll
            for (int o = 16; o > 0; o >>= 1)
                p += __shfl_xor_sync(~0u, p, o);
            if (lane == 0) sm_wred[warp * 9 + h] = p;
        }
        __syncthreads();   // S2

        // ---- D: ctx (warp -> 4 e's); p-chunk outer, e inner (LDS x1) ----
        {
            const int h = warp >> 2;
            float sv = sm_wred[lane * 9 + h];
            #pragma unroll
            for (int o = 16; o > 0; o >>= 1)
                sv += __shfl_xor_sync(~0u, sv, o);
            const float inv = 1.0f / sv;
            float acc[4] = {0.f, 0.f, 0.f, 0.f};
            const uint2* vt = g_V4 + (size_t)(b * EE + warp * 4) * (NPAD / 4);
            #pragma unroll
            for (int k = 0; k < 8; ++k) {
                const int idx = k * 32 + lane;
                const float4 pp = *(const float4*)&smp[h * NPAD + 4 * idx];
                #pragma unroll
                for (int i = 0; i < 4; ++i) {
                    const uint2 r = vt[i * (NPAD / 4) + idx];
                    const float2 v0 = __bfloat1622float2(*(const __nv_bfloat162*)&r.x);
                    const float2 v1 = __bfloat1622float2(*(const __nv_bfloat162*)&r.y);
                    acc[i] += pp.x * v0.x + pp.y * v0.y + pp.z * v1.x + pp.w * v1.y;
                }
            }
            #pragma unroll
            for (int i = 0; i < 4; ++i) {
                #pragma unroll
                for (int o = 16; o > 0; o >>= 1)
                    acc[i] += __shfl_xor_sync(~0u, acc[i], o);
                if (lane == 0) sm_ctx[warp * 4 + i] = acc[i] * inv;
            }
        }
        __syncthreads();   // S3

        // ---- F: logits = ctx.G + blk; fused argmax + sum exp ----
        {
            float a = sm_blk[t];
            #pragma unroll
            for (int c4 = 0; c4 < 32; ++c4) {
                const uint2 r = gq[(size_t)c4 * NPAD];
                const float2 l0 = __bfloat1622float2(*(const __nv_bfloat162*)&r.x);
                const float2 l1 = __bfloat1622float2(*(const __nv_bfloat162*)&r.y);
                const float4 xv = *(const float4*)&sm_ctx[4 * c4];
                a += xv.x * l0.x + xv.y * l0.y + xv.z * l1.x + xv.w * l1.y;
            }
            float mv = msk ? NEGV : a;
            int   mi = t;
            float s  = msk ? 0.f : __expf(tanh_fast(a * SCALE) * 10.0f);
            #pragma unroll
            for (int o = 16; o > 0; o >>= 1) {
                const float ov = __shfl_xor_sync(~0u, mv, o);
                const int   oi = __shfl_xor_sync(~0u, mi, o);
                s += __shfl_xor_sync(~0u, s, o);
                if (ov > mv || (ov == mv && oi < mi)) { mv = ov; mi = oi; }
            }
            if (lane == 0) {
                sm_wred[warp * 9 + 0] = mv;
                sm_wred[warp * 9 + 1] = s;
                sm_iwred[warp] = mi;
            }
        }
        __syncthreads();   // S4

        // ---- final reduce, redundant in every warp: all threads learn mi ----
        {
            float mv = sm_wred[lane * 9 + 0];
            float s  = sm_wred[lane * 9 + 1];
            int   mi = sm_iwred[lane];
            #pragma unroll
            for (int o = 16; o > 0; o >>= 1) {
                const float ov = __shfl_xor_sync(~0u, mv, o);
                const int   oi = __shfl_xor_sync(~0u, mi, o);
                s += __shfl_xor_sync(~0u, s, o);
                if (ov > mv || (ov == mv && oi < mi)) { mv = ov; mi = oi; }
            }
            if (t == 0) {
                total += tanhf(mv * SCALE) * 10.0f - logf(s);  // precise winner
                sm_mask[mi] = 1;
            }
            cur = mi;
        }
        // next S1 publishes sm_mask before it is read again
    }

    if (t == 0) out[b] = total;
}

// ---------------------------------------------------------------------------
extern "C" void kernel_launch(void* const* d_in, const int* in_sizes, int n_in,
                              void* d_out, int out_size) {
    const float* node  = (const float*)d_in[0];
    const float* graph = (const float*)d_in[1];
    const float* Wqkv  = (const float*)d_in[2];
    const float* bqkv  = (const float*)d_in[3];
    const float* Wfix  = (const float*)d_in[4];
    const float* bfix  = (const float*)d_in[5];
    const float* Wstep = (const float*)d_in[6];
    const float* bstep = (const float*)d_in[7];
    const float* Wmlp  = (const float*)d_in[8];
    const float* bmlp  = (const float*)d_in[9];
    float* out = (float*)d_out;

    dim3 blk2(16, 16);
    qkv_gemm<<<dim3(6, 16, BB), blk2>>>(node, Wqkv, bqkv);
    sk_gemm <<<dim3(2, 16, BB), blk2>>>(node, Wstep);
    g_gemm  <<<dim3(2, 16, BB), blk2>>>(Wmlp);
    blk_kernel <<<BB, NPAD>>>(bmlp);
    qbase_kernel<<<BB, EE>>>(graph, node, Wfix, bfix, Wstep, bstep);
    decode_loop<<<BB, 1024>>>(out);
}

// round 6
// speedup vs baseline: 4.2943x; 1.4910x over previous
#include <cuda_runtime.h>
#include <cuda_bf16.h>
#include <math.h>

#define BB   128
#define NTOK 1000
#define NPAD 1024
#define EE   128
#define HH   8
#define NEGV (-1000000000.0f)
#define SCALE 0.25f

// K, V, G all quad-interleaved over feature: (b,e,n) -> bf16
//   ((b*32 + (e>>2)) * NPAD + n) * 4 + (e&3)
// i.e. per (b, quad) a row of NPAD uint2 entries (one uint2 = 4 features of one token).
__device__ uint2 g_K4[BB * 32 * NPAD];
__device__ uint2 g_V4[BB * 32 * NPAD];
__device__ uint2 g_G4[BB * 32 * NPAD];
__device__ __nv_bfloat16 g_LKp[BB * EE * NPAD];
__device__ float g_SK   [(size_t)BB * NTOK * EE];   // node @ Wstep[128:]
__device__ float g_qbase[BB * EE];
__device__ float g_blk  [BB * NPAD];                // bmlp . LK[:,n]

// ---------------------------------------------------------------------------
// Precompute 1: qkv = node @ Wqkv + bqkv -> K4 / V4 / LKp
// ---------------------------------------------------------------------------
__global__ void qkv_gemm(const float* __restrict__ node,
                         const float* __restrict__ W,
                         const float* __restrict__ bias) {
    __shared__ float As[16][64];
    __shared__ float Bs[16][64];
    const int b  = blockIdx.z;
    const int n0 = blockIdx.y * 64;
    const int e0 = blockIdx.x * 64;
    const int tx = threadIdx.x, ty = threadIdx.y;
    const int t  = ty * 16 + tx;
    const int an = t >> 2, ak = (t & 3) * 4;
    const int bk = t >> 4, be = (t & 15) * 4;

    float acc[4][4] = {};
    for (int k0 = 0; k0 < 128; k0 += 16) {
        float4 av;
        const int n = n0 + an;
        if (n < NTOK) av = *(const float4*)&node[((size_t)b * NTOK + n) * EE + k0 + ak];
        else          av = make_float4(0.f, 0.f, 0.f, 0.f);
        As[ak + 0][an] = av.x; As[ak + 1][an] = av.y;
        As[ak + 2][an] = av.z; As[ak + 3][an] = av.w;
        *(float4*)&Bs[bk][be] = *(const float4*)&W[(size_t)(k0 + bk) * 384 + e0 + be];
        __syncthreads();
        #pragma unroll
        for (int kk = 0; kk < 16; ++kk) {
            float ar[4], br[4];
            #pragma unroll
            for (int i = 0; i < 4; ++i) ar[i] = As[kk][ty * 4 + i];
            #pragma unroll
            for (int j = 0; j < 4; ++j) br[j] = Bs[kk][tx * 4 + j];
            #pragma unroll
            for (int i = 0; i < 4; ++i)
                #pragma unroll
                for (int j = 0; j < 4; ++j) acc[i][j] += ar[i] * br[j];
        }
        __syncthreads();
    }

    __nv_bfloat16* K = (__nv_bfloat16*)g_K4;
    __nv_bfloat16* V = (__nv_bfloat16*)g_V4;
    #pragma unroll
    for (int i = 0; i < 4; ++i) {
        const int n = n0 + ty * 4 + i;
        if (n >= NTOK) continue;
        #pragma unroll
        for (int j = 0; j < 4; ++j) {
            const int e3 = e0 + tx * 4 + j;
            const __nv_bfloat16 bv = __float2bfloat16(acc[i][j] + bias[e3]);
            if (e3 < 128) {
                const int e = e3;
                K[((size_t)(b * 32 + (e >> 2)) * NPAD + n) * 4 + (e & 3)] = bv;
            } else if (e3 < 256) {
                const int e = e3 - 128;
                V[((size_t)(b * 32 + (e >> 2)) * NPAD + n) * 4 + (e & 3)] = bv;
            } else {
                const int e = e3 - 256;
                g_LKp[(size_t)(b * EE + e) * NPAD + n] = bv;
            }
        }
    }
}

// ---------------------------------------------------------------------------
// Precompute 2: SK[b][n][e] = node[b,n] @ Wstep[128:256]  (fp32)
// ---------------------------------------------------------------------------
__global__ void sk_gemm(const float* __restrict__ node,
                        const float* __restrict__ Wstep) {
    __shared__ float As[16][64];
    __shared__ float Bs[16][64];
    const float* W2 = Wstep + 128 * EE;
    const int b  = blockIdx.z;
    const int n0 = blockIdx.y * 64;
    const int e0 = blockIdx.x * 64;
    const int tx = threadIdx.x, ty = threadIdx.y;
    const int t  = ty * 16 + tx;
    const int an = t >> 2, ak = (t & 3) * 4;
    const int bk = t >> 4, be = (t & 15) * 4;

    float acc[4][4] = {};
    for (int k0 = 0; k0 < 128; k0 += 16) {
        float4 av;
        const int n = n0 + an;
        if (n < NTOK) av = *(const float4*)&node[((size_t)b * NTOK + n) * EE + k0 + ak];
        else          av = make_float4(0.f, 0.f, 0.f, 0.f);
        As[ak + 0][an] = av.x; As[ak + 1][an] = av.y;
        As[ak + 2][an] = av.z; As[ak + 3][an] = av.w;
        *(float4*)&Bs[bk][be] = *(const float4*)&W2[(size_t)(k0 + bk) * EE + e0 + be];
        __syncthreads();
        #pragma unroll
        for (int kk = 0; kk < 16; ++kk) {
            float ar[4], br[4];
            #pragma unroll
            for (int i = 0; i < 4; ++i) ar[i] = As[kk][ty * 4 + i];
            #pragma unroll
            for (int j = 0; j < 4; ++j) br[j] = Bs[kk][tx * 4 + j];
            #pragma unroll
            for (int i = 0; i < 4; ++i)
                #pragma unroll
                for (int j = 0; j < 4; ++j) acc[i][j] += ar[i] * br[j];
        }
        __syncthreads();
    }
    #pragma unroll
    for (int i = 0; i < 4; ++i) {
        const int n = n0 + ty * 4 + i;
        if (n >= NTOK) continue;
        #pragma unroll
        for (int j = 0; j < 4; ++j)
            g_SK[((size_t)b * NTOK + n) * EE + e0 + tx * 4 + j] = acc[i][j];
    }
}

// ---------------------------------------------------------------------------
// Precompute 3: G[b][c][n] = Wmlp[c][:] . LK[b][:][n]  -> quad-interleaved bf16
// ---------------------------------------------------------------------------
__global__ void g_gemm(const float* __restrict__ Wmlp) {
    __shared__ float As[16][64];   // [e][c]
    __shared__ float Bs[16][64];   // [e][n]
    const int b  = blockIdx.z;
    const int n0 = blockIdx.y * 64;
    const int c0 = blockIdx.x * 64;
    const int tx = threadIdx.x, ty = threadIdx.y;
    const int t  = ty * 16 + tx;
    const int ac = t >> 2, ae = (t & 3) * 4;
    const int bk = t >> 4, bn = (t & 15) * 4;

    float acc[4][4] = {};
    for (int k0 = 0; k0 < 128; k0 += 16) {
        const float4 av = *(const float4*)&Wmlp[(size_t)(c0 + ac) * EE + k0 + ae];
        As[ae + 0][ac] = av.x; As[ae + 1][ac] = av.y;
        As[ae + 2][ac] = av.z; As[ae + 3][ac] = av.w;
        const uint2 r = *(const uint2*)&g_LKp[(size_t)(b * EE + k0 + bk) * NPAD + n0 + bn];
        const float2 v0 = __bfloat1622float2(*(const __nv_bfloat162*)&r.x);
        const float2 v1 = __bfloat1622float2(*(const __nv_bfloat162*)&r.y);
        Bs[bk][bn + 0] = v0.x; Bs[bk][bn + 1] = v0.y;
        Bs[bk][bn + 2] = v1.x; Bs[bk][bn + 3] = v1.y;
        __syncthreads();
        #pragma unroll
        for (int kk = 0; kk < 16; ++kk) {
            float ar[4], br[4];
            #pragma unroll
            for (int i = 0; i < 4; ++i) ar[i] = As[kk][ty * 4 + i];
            #pragma unroll
            for (int j = 0; j < 4; ++j) br[j] = Bs[kk][tx * 4 + j];
            #pragma unroll
            for (int i = 0; i < 4; ++i)
                #pragma unroll
                for (int j = 0; j < 4; ++j) acc[i][j] += ar[i] * br[j];
        }
        __syncthreads();
    }
    __nv_bfloat16* G = (__nv_bfloat16*)g_G4;
    #pragma unroll
    for (int i = 0; i < 4; ++i) {
        const int c = c0 + ty * 4 + i;
        #pragma unroll
        for (int j = 0; j < 4; ++j) {
            const int n = n0 + tx * 4 + j;
            G[((size_t)(b * 32 + (c >> 2)) * NPAD + n) * 4 + (c & 3)] =
                __float2bfloat16(acc[i][j]);
        }
    }
}

// ---------------------------------------------------------------------------
// Precompute 4: blk[b][n] = bmlp . LK[b][:][n]
// ---------------------------------------------------------------------------
__global__ void blk_kernel(const float* __restrict__ bmlp) {
    const int b = blockIdx.x, n = threadIdx.x;
    __shared__ float bm[EE];
    if (n < EE) bm[n] = bmlp[n];
    __syncthreads();
    float a = 0.f;
    #pragma unroll 8
    for (int e = 0; e < EE; ++e)
        a += bm[e] * __bfloat162float(g_LKp[(size_t)(b * EE + e) * NPAD + n]);
    g_blk[b * NPAD + n] = a;
}

// ---------------------------------------------------------------------------
// Precompute 5: qbase = graph@Wfix + bfix + bstep + first@Wstep[:128]
// ---------------------------------------------------------------------------
__global__ void qbase_kernel(const float* __restrict__ g,
                             const float* __restrict__ node,
                             const float* __restrict__ Wfix,
                             const float* __restrict__ bfix,
                             const float* __restrict__ Wstep,
                             const float* __restrict__ bstep) {
    const int b = blockIdx.x, e = threadIdx.x;
    __shared__ float gs[EE], fs[EE];
    gs[e] = g[b * EE + e];
    fs[e] = node[(size_t)b * NTOK * EE + e];
    __syncthreads();
    float a = bfix[e] + bstep[e];
    #pragma unroll 4
    for (int k = 0; k < EE; ++k) {
        a += gs[k] * Wfix[(size_t)k * EE + e];
        a += fs[k] * Wstep[(size_t)k * EE + e];
    }
    g_qbase[b * EE + e] = a;
}

__device__ __forceinline__ float tanh_fast(float x) {
    float r;
    asm("tanh.approx.f32 %0, %1;" : "=f"(r) : "f"(x));
    return r;
}

// ---------------------------------------------------------------------------
// Persistent decode loop with periodic active-token compaction.
// ---------------------------------------------------------------------------
__global__ void __launch_bounds__(1024, 1)
decode_loop(float* __restrict__ out) {
    const int b    = blockIdx.x;
    const int t    = threadIdx.x;
    const int warp = t >> 5, lane = t & 31;

    __shared__ __align__(16) float smp[HH * NPAD];   // 32 KB
    __shared__ float sm_blk[NPAD];                   // 4 KB
    __shared__ int   sm_idx[NPAD];                   // 4 KB: compact slot -> original n
    __shared__ float sm_wred[32 * 9];
    __shared__ int   sm_iwred[32];
    __shared__ __align__(16) float sm_q[EE];
    __shared__ __align__(16) float sm_ctx[EE];
    __shared__ float sm_qbase[EE];
    __shared__ unsigned char sm_mask[NPAD];
    __shared__ int   sm_cbase[32];
    __shared__ int   sm_newM;

    if (t < EE) sm_qbase[t] = g_qbase[b * EE + t];
    sm_blk[t]  = g_blk[b * NPAD + t];
    sm_idx[t]  = t;
    sm_mask[t] = (t == 0 || t >= NTOK) ? 1 : 0;
    __syncthreads();

    const uint2* kq = g_K4 + (size_t)b * 32 * NPAD + t;
    const uint2* gq = g_G4 + (size_t)b * 32 * NPAD + t;
    int   cur   = 0;       // original index of last selected node
    float total = 0.f;
    int   M_pad = NPAD;    // active slots (rounded to 128); tokens live in [0, M_pad)
    int   nch   = NPAD / 32;

    #pragma unroll 1
    for (int step = 0; step < NTOK - 1; ++step) {
        // ---- q row: qbase + SK[cur] ----
        if (t < EE)
            sm_q[t] = sm_qbase[t] + g_SK[((size_t)b * NTOK + cur) * EE + t];
        __syncthreads();   // S1 (publishes mask update / compaction from prev iter)

        // ---- C: scores, p = exp (no max-shift), per-warp head sums ----
        const bool msk = sm_mask[t];
        if (t < M_pad) {
            #pragma unroll
            for (int h = 0; h < HH; ++h) {
                float a = 0.f;
                #pragma unroll
                for (int c = 0; c < 4; ++c) {
                    const uint2 r = kq[(size_t)(4 * h + c) * NPAD];
                    const float2 k0 = __bfloat1622float2(*(const __nv_bfloat162*)&r.x);
                    const float2 k1 = __bfloat1622float2(*(const __nv_bfloat162*)&r.y);
                    const float4 qv = *(const float4*)&sm_q[h * 16 + 4 * c];
                    a += qv.x * k0.x + qv.y * k0.y + qv.z * k1.x + qv.w * k1.y;
                }
                float p = msk ? 0.f : __expf(a * SCALE);
                smp[h * NPAD + t] = p;
                #pragma unroll
                for (int o = 16; o > 0; o >>= 1)
                    p += __shfl_xor_sync(~0u, p, o);
                if (lane == 0) sm_wred[warp * 9 + h] = p;
            }
        } else if (lane == 0) {
            #pragma unroll
            for (int h = 0; h < HH; ++h) sm_wred[warp * 9 + h] = 0.f;
        }
        __syncthreads();   // S2

        // ---- D: ctx; warp w owns feature quad w (e = 4w..4w+3), h = w>>2 ----
        {
            const int h = warp >> 2;
            float sv = sm_wred[lane * 9 + h];
            #pragma unroll
            for (int o = 16; o > 0; o >>= 1)
                sv += __shfl_xor_sync(~0u, sv, o);
            const float inv = 1.0f / sv;
            float a0 = 0.f, a1 = 0.f, a2 = 0.f, a3 = 0.f;
            const uint2* vt = g_V4 + ((size_t)b * 32 + warp) * NPAD;
            const float* pp = smp + h * NPAD;
            #pragma unroll 4
            for (int n = lane; n < M_pad; n += 32) {
                const uint2 r = vt[n];
                const float p = pp[n];
                const float2 v0 = __bfloat1622float2(*(const __nv_bfloat162*)&r.x);
                const float2 v1 = __bfloat1622float2(*(const __nv_bfloat162*)&r.y);
                a0 += p * v0.x; a1 += p * v0.y; a2 += p * v1.x; a3 += p * v1.y;
            }
            #pragma unroll
            for (int o = 16; o > 0; o >>= 1) {
                a0 += __shfl_xor_sync(~0u, a0, o);
                a1 += __shfl_xor_sync(~0u, a1, o);
                a2 += __shfl_xor_sync(~0u, a2, o);
                a3 += __shfl_xor_sync(~0u, a3, o);
            }
            if (lane == 0) {
                sm_ctx[warp * 4 + 0] = a0 * inv;
                sm_ctx[warp * 4 + 1] = a1 * inv;
                sm_ctx[warp * 4 + 2] = a2 * inv;
                sm_ctx[warp * 4 + 3] = a3 * inv;
            }
        }
        __syncthreads();   // S3

        // ---- F: logits = ctx.G + blk; fused argmax + sum exp ----
        {
            float mv = NEGV, s = 0.f;
            int   mi = t;
            if (t < M_pad) {
                float a = sm_blk[t];
                #pragma unroll
                for (int c4 = 0; c4 < 32; ++c4) {
                    const uint2 r = gq[(size_t)c4 * NPAD];
                    const float2 l0 = __bfloat1622float2(*(const __nv_bfloat162*)&r.x);
                    const float2 l1 = __bfloat1622float2(*(const __nv_bfloat162*)&r.y);
                    const float4 xv = *(const float4*)&sm_ctx[4 * c4];
                    a += xv.x * l0.x + xv.y * l0.y + xv.z * l1.x + xv.w * l1.y;
                }
                if (!msk) {
                    mv = a;
                    s  = __expf(tanh_fast(a * SCALE) * 10.0f);
                }
                #pragma unroll
                for (int o = 16; o > 0; o >>= 1) {
                    const float ov = __shfl_xor_sync(~0u, mv, o);
                    const int   oi = __shfl_xor_sync(~0u, mi, o);
                    s += __shfl_xor_sync(~0u, s, o);
                    if (ov > mv || (ov == mv && oi < mi)) { mv = ov; mi = oi; }
                }
            }
            if (lane == 0) {
                sm_wred[warp * 9 + 0] = mv;
                sm_wred[warp * 9 + 1] = s;
                sm_iwred[warp] = mi;
            }
        }
        __syncthreads();   // S4

        // ---- final reduce, redundant in every warp ----
        {
            float mv = sm_wred[lane * 9 + 0];
            float s  = sm_wred[lane * 9 + 1];
            int   mi = sm_iwred[lane];
            #pragma unroll
            for (int o = 16; o > 0; o >>= 1) {
                const float ov = __shfl_xor_sync(~0u, mv, o);
                const int   oi = __shfl_xor_sync(~0u, mi, o);
                s += __shfl_xor_sync(~0u, s, o);
                if (ov > mv || (ov == mv && oi < mi)) { mv = ov; mi = oi; }
            }
            if (t == 0) {
                total += tanhf(mv * SCALE) * 10.0f - logf(s);  // precise winner
                sm_mask[mi] = 1;
            }
            cur = sm_idx[mi];   // original index (broadcast LDS)
        }

        // ---- periodic stable compaction of active tokens ----
        if (((step + 1) & 63) == 0) {
            __syncthreads();                 // CS1: mask/idx reads done, mask final
            if (warp == 0) {
                int cnt = 0;
                if (lane < nch) {
                    const unsigned char* mp = sm_mask + lane * 32;
                    #pragma unroll
                    for (int j = 0; j < 32; ++j) cnt += (mp[j] == 0);
                }
                int inc = cnt;
                #pragma unroll
                for (int o = 1; o < 32; o <<= 1) {
                    const int v = __shfl_up_sync(~0u, inc, o);
                    if (lane >= o) inc += v;
                }
                if (lane < nch) sm_cbase[lane] = inc - cnt;
                if (lane == nch - 1) sm_newM = inc;
            }
            __syncthreads();                 // CS2
            {
                uint2* rows[3] = {
                    g_K4 + ((size_t)b * 32 + warp) * NPAD,
                    g_V4 + ((size_t)b * 32 + warp) * NPAD,
                    g_G4 + ((size_t)b * 32 + warp) * NPAD };
                #pragma unroll
                for (int a = 0; a < 3; ++a) {
                    uint2* row = rows[a];
                    for (int c = 0; c < nch; ++c) {
                        const int n = c * 32 + lane;
                        const uint2 v = row[n];
                        const bool keep = (sm_mask[n] == 0);
                        const unsigned bal = __ballot_sync(~0u, keep);
                        if (keep)
                            row[sm_cbase[c] + __popc(bal & ((1u << lane) - 1))] = v;
                    }
                }
                if (warp == 0) {             // compact blk (smem, in-place)
                    for (int c = 0; c < nch; ++c) {
                        const int n = c * 32 + lane;
                        const float v = sm_blk[n];
                        const bool keep = (sm_mask[n] == 0);
                        const unsigned bal = __ballot_sync(~0u, keep);
                        if (keep)
                            sm_blk[sm_cbase[c] + __popc(bal & ((1u << lane) - 1))] = v;
                    }
                }
                if (warp == 1) {             // compact idx map
                    for (int c = 0; c < nch; ++c) {
                        const int n = c * 32 + lane;
                        const int v = sm_idx[n];
                        const bool keep = (sm_mask[n] == 0);
                        const unsigned bal = __ballot_sync(~0u, keep);
                        if (keep)
                            sm_idx[sm_cbase[c] + __popc(bal & ((1u << lane) - 1))] = v;
                    }
                }
            }
            __syncthreads();                 // CS3: moves done
            const int M = sm_newM;
            M_pad = (M + 127) & ~127;
            nch   = M_pad >> 5;
            sm_mask[t] = (t >= M) ? 1 : 0;   // all active slots unmasked
            // next S1 publishes before any read
        }
    }

    if (t == 0) out[b] = total;
}

// ---------------------------------------------------------------------------
extern "C" void kernel_launch(void* const* d_in, const int* in_sizes, int n_in,
                              void* d_out, int out_size) {
    const float* node  = (const float*)d_in[0];
    const float* graph = (const float*)d_in[1];
    const float* Wqkv  = (const float*)d_in[2];
    const float* bqkv  = (const float*)d_in[3];
    const float* Wfix  = (const float*)d_in[4];
    const float* bfix  = (const float*)d_in[5];
    const float* Wstep = (const float*)d_in[6];
    const float* bstep = (const float*)d_in[7];
    const float* Wmlp  = (const float*)d_in[8];
    const float* bmlp  = (const float*)d_in[9];
    float* out = (float*)d_out;

    dim3 blk2(16, 16);
    qkv_gemm<<<dim3(6, 16, BB), blk2>>>(node, Wqkv, bqkv);
    sk_gemm <<<dim3(2, 16, BB), blk2>>>(node, Wstep);
    g_gemm  <<<dim3(2, 16, BB), blk2>>>(Wmlp);
    blk_kernel <<<BB, NPAD>>>(bmlp);
    qbase_kernel<<<BB, EE>>>(graph, node, Wfix, bfix, Wstep, bstep);
    decode_loop<<<BB, 1024>>>(out);
}